// round 1
// baseline (speedup 1.0000x reference)
#include <cuda_runtime.h>
#include <cuda_bf16.h>
#include <math.h>

// Problem constants (fixed by the dataset)
#define BB   32
#define NSEQ 1024
#define CC   768
#define HH   12
#define DD   64
#define OUTF 2496            // 3C + 3D
#define XCATC 832            // C + D
#define MROWS (BB*NSEQ)      // 32768

// SCALE = 9^-0.5 = 1/3 ; inner e = -v/N * SCALE
#define ESC_CONST (-(1.0f/1024.0f)*(1.0f/3.0f))

// Scratch (device globals -> no allocation)
__device__ float g_qkv[(size_t)MROWS * OUTF];   // [32768, 2496]
__device__ float g_xcat[(size_t)MROWS * XCATC]; // [32768, 832]

// ---------------------------------------------------------------------------
// Generic SGEMM: C[M,N] = A[M,K] @ B[K,N] + bias[N]
// 128x128 block tile, BK=16, 256 threads, 8x8 per thread (2x2 float4 groups).
// Requires: M % 128 == 0, K % 16 == 0, N % 4 == 0. N edge guarded.
// ---------------------------------------------------------------------------
__global__ __launch_bounds__(256) void gemm_bias_kernel(
    const float* __restrict__ A, const float* __restrict__ B,
    const float* __restrict__ bias, float* __restrict__ C,
    int M, int N, int K)
{
    __shared__ __align__(16) float As[16][128];
    __shared__ __align__(16) float Bs[16][128];
    const int tid = threadIdx.x;
    const int tx = tid & 15, ty = tid >> 4;
    const int brow = blockIdx.y * 128;
    const int bcol = blockIdx.x * 128;

    float acc[8][8];
#pragma unroll
    for (int i = 0; i < 8; i++)
#pragma unroll
        for (int j = 0; j < 8; j++) acc[i][j] = 0.f;

    const int ar0 = tid >> 2;          // A row within tile (0..63, +64)
    const int ak  = (tid & 3) * 4;     // A k offset (0,4,8,12)
    const int br0 = tid >> 5;          // B row within tile (0..7, +8)
    const int bc  = (tid & 31) * 4;    // B col (0..124)

    for (int k0 = 0; k0 < K; k0 += 16) {
#pragma unroll
        for (int i = 0; i < 2; i++) {
            int r = ar0 + i * 64;
            float4 va = *(const float4*)&A[(size_t)(brow + r) * K + k0 + ak];
            As[ak + 0][r] = va.x; As[ak + 1][r] = va.y;
            As[ak + 2][r] = va.z; As[ak + 3][r] = va.w;
        }
#pragma unroll
        for (int i = 0; i < 2; i++) {
            int r = br0 + i * 8;
            int gc = bcol + bc;
            float4 vb = make_float4(0.f, 0.f, 0.f, 0.f);
            if (gc < N) vb = *(const float4*)&B[(size_t)(k0 + r) * N + gc];
            *(float4*)&Bs[r][bc] = vb;
        }
        __syncthreads();
#pragma unroll
        for (int kk = 0; kk < 16; kk++) {
            float4 a0 = *(const float4*)&As[kk][ty * 4];
            float4 a1 = *(const float4*)&As[kk][ty * 4 + 64];
            float4 b0 = *(const float4*)&Bs[kk][tx * 4];
            float4 b1 = *(const float4*)&Bs[kk][tx * 4 + 64];
            float ar[8] = {a0.x, a0.y, a0.z, a0.w, a1.x, a1.y, a1.z, a1.w};
            float br[8] = {b0.x, b0.y, b0.z, b0.w, b1.x, b1.y, b1.z, b1.w};
#pragma unroll
            for (int i = 0; i < 8; i++)
#pragma unroll
                for (int j = 0; j < 8; j++) acc[i][j] += ar[i] * br[j];
        }
        __syncthreads();
    }

#pragma unroll
    for (int ci = 0; ci < 2; ci++) {
        int gc = bcol + ci * 64 + tx * 4;
        if (gc >= N) continue;
        float4 bv = *(const float4*)&bias[gc];
#pragma unroll
        for (int ri = 0; ri < 2; ri++) {
#pragma unroll
            for (int i = 0; i < 4; i++) {
                int gr = brow + ri * 64 + ty * 4 + i;
                float4 o;
                o.x = acc[ri * 4 + i][ci * 4 + 0] + bv.x;
                o.y = acc[ri * 4 + i][ci * 4 + 1] + bv.y;
                o.z = acc[ri * 4 + i][ci * 4 + 2] + bv.z;
                o.w = acc[ri * 4 + i][ci * 4 + 3] + bv.w;
                *(float4*)&C[(size_t)gr * N + gc] = o;
            }
        }
    }
}

// ---------------------------------------------------------------------------
// Fused per-(b,h) SwiGLU fast-weight update + x1 apply.
// Grid: 384 blocks (b*12+h), 256 threads.
//  phase 1: stream k1/v1 tiles (16 rows), z1/z2 = k@w1/w2, build ea/eg,
//           accumulate g1/g2 (4x4 per thread).
//  phase 2: column-norm (atomicAdd to smem), update w1s/w2s in place.
//  phase 3: stream q1 tiles, x1 = (q@w1u)*silu(q@w2u) -> g_xcat cols [h*64..].
// ---------------------------------------------------------------------------
__global__ __launch_bounds__(256) void swiglu_x1_kernel(
    const float* __restrict__ w1, const float* __restrict__ w2)
{
    __shared__ __align__(16) float w1s[DD * DD];    // 4096
    __shared__ __align__(16) float w2s[DD * DD];    // 4096
    __shared__ __align__(16) float ks[16 * DD];     // 1024
    __shared__ __align__(16) float eas[16 * DD];    // 1024
    __shared__ __align__(16) float egs[16 * DD];    // 1024
    __shared__ float colsum[2 * DD];                // 128

    const int b = blockIdx.x / HH;
    const int h = blockIdx.x % HH;
    const int tid = threadIdx.x;
    const int d0 = (tid >> 4) << 2;   // row group (g accumulation)
    const int e0 = (tid & 15) << 2;   // col group
    const int zrow = tid >> 4;        // row for z-compute (0..15)

    for (int i = tid; i < DD * DD; i += 256) {
        w1s[i] = w1[h * DD * DD + i];
        w2s[i] = w2[h * DD * DD + i];
    }
    if (tid < 2 * DD) colsum[tid] = 0.f;

    float g1[4][4], g2[4][4];
#pragma unroll
    for (int i = 0; i < 4; i++)
#pragma unroll
        for (int j = 0; j < 4; j++) { g1[i][j] = 0.f; g2[i][j] = 0.f; }

    __syncthreads();

    for (int n0 = 0; n0 < NSEQ; n0 += 16) {
        // load k tile [16,64]
        for (int i = tid; i < 16 * DD; i += 256) {
            int n = i >> 6, d = i & 63;
            ks[i] = g_qkv[(size_t)(b * NSEQ + n0 + n) * OUTF + CC + h * DD + d];
        }
        __syncthreads();

        // z1,z2 for (zrow, e0..e0+3)
        float z1[4] = {0.f, 0.f, 0.f, 0.f}, z2[4] = {0.f, 0.f, 0.f, 0.f};
        const float* krow = ks + zrow * DD;
#pragma unroll 16
        for (int d = 0; d < DD; d++) {
            float kv = krow[d];
            float4 w1v = *(const float4*)&w1s[d * DD + e0];
            float4 w2v = *(const float4*)&w2s[d * DD + e0];
            z1[0] += kv * w1v.x; z1[1] += kv * w1v.y; z1[2] += kv * w1v.z; z1[3] += kv * w1v.w;
            z2[0] += kv * w2v.x; z2[1] += kv * w2v.y; z2[2] += kv * w2v.z; z2[3] += kv * w2v.w;
        }
        // v read straight from global (coalesced within 16-lane groups)
        float4 vv = *(const float4*)&g_qkv[(size_t)(b * NSEQ + n0 + zrow) * OUTF + 2 * CC + h * DD + e0];
        float vj[4] = {vv.x, vv.y, vv.z, vv.w};
        float4 eav, egv;
        float* eap = (float*)&eav; float* egp = (float*)&egv;
#pragma unroll
        for (int j = 0; j < 4; j++) {
            float ev = ESC_CONST * vj[j];
            float s = 1.f / (1.f + expf(-z2[j]));
            float a = z2[j] * s;
            eap[j] = ev * a;
            egp[j] = ev * z1[j] * (s * (1.f + z2[j] * (1.f - s)));
        }
        *(float4*)&eas[zrow * DD + e0] = eav;
        *(float4*)&egs[zrow * DD + e0] = egv;
        __syncthreads();

        // g1[d][e] += k[n][d]*ea[n][e] ; g2 likewise with eg
#pragma unroll
        for (int nn = 0; nn < 16; nn++) {
            float4 ka = *(const float4*)&ks[nn * DD + d0];
            float4 ea = *(const float4*)&eas[nn * DD + e0];
            float4 eg = *(const float4*)&egs[nn * DD + e0];
            float kr[4] = {ka.x, ka.y, ka.z, ka.w};
            float er[4] = {ea.x, ea.y, ea.z, ea.w};
            float gr[4] = {eg.x, eg.y, eg.z, eg.w};
#pragma unroll
            for (int i = 0; i < 4; i++)
#pragma unroll
                for (int j = 0; j < 4; j++) {
                    g1[i][j] += kr[i] * er[j];
                    g2[i][j] += kr[i] * gr[j];
                }
        }
        __syncthreads();
    }

    // column sums of squares (norm over d axis)
#pragma unroll
    for (int j = 0; j < 4; j++) {
        float s1 = 0.f, s2 = 0.f;
#pragma unroll
        for (int i = 0; i < 4; i++) { s1 += g1[i][j] * g1[i][j]; s2 += g2[i][j] * g2[i][j]; }
        atomicAdd(&colsum[e0 + j], s1);
        atomicAdd(&colsum[DD + e0 + j], s2);
    }
    __syncthreads();

    // update weights in smem: w -= g / (||col|| + 1)
#pragma unroll
    for (int j = 0; j < 4; j++) {
        float inv1 = 1.f / (sqrtf(colsum[e0 + j]) + 1.f);
        float inv2 = 1.f / (sqrtf(colsum[DD + e0 + j]) + 1.f);
#pragma unroll
        for (int i = 0; i < 4; i++) {
            w1s[(d0 + i) * DD + e0 + j] -= g1[i][j] * inv1;
            w2s[(d0 + i) * DD + e0 + j] -= g2[i][j] * inv2;
        }
    }
    __syncthreads();

    // phase 3: x1 = (q@w1u) * silu(q@w2u)
    for (int n0 = 0; n0 < NSEQ; n0 += 16) {
        for (int i = tid; i < 16 * DD; i += 256) {
            int n = i >> 6, d = i & 63;
            ks[i] = g_qkv[(size_t)(b * NSEQ + n0 + n) * OUTF + h * DD + d];  // q1
        }
        __syncthreads();
        float y1[4] = {0.f, 0.f, 0.f, 0.f}, y2[4] = {0.f, 0.f, 0.f, 0.f};
        const float* qrow = ks + zrow * DD;
#pragma unroll 16
        for (int d = 0; d < DD; d++) {
            float qv = qrow[d];
            float4 w1v = *(const float4*)&w1s[d * DD + e0];
            float4 w2v = *(const float4*)&w2s[d * DD + e0];
            y1[0] += qv * w1v.x; y1[1] += qv * w1v.y; y1[2] += qv * w1v.z; y1[3] += qv * w1v.w;
            y2[0] += qv * w2v.x; y2[1] += qv * w2v.y; y2[2] += qv * w2v.z; y2[3] += qv * w2v.w;
        }
        float4 o;
        float* op = (float*)&o;
#pragma unroll
        for (int j = 0; j < 4; j++) {
            float s = 1.f / (1.f + expf(-y2[j]));
            op[j] = y1[j] * (y2[j] * s);   // y1 * silu(y2)
        }
        *(float4*)&g_xcat[(size_t)(b * NSEQ + n0 + zrow) * XCATC + h * DD + e0] = o;
        __syncthreads();
    }
}

// ---------------------------------------------------------------------------
// Fused per-(b,d) depthwise-conv fast-weight update + conv apply.
// Grid: 2048 blocks (b*64+d), 256 threads.
// ---------------------------------------------------------------------------
__global__ __launch_bounds__(256) void dwc_x2_kernel(const float* __restrict__ w3)
{
    __shared__ float q2s[1024], k2s[1024], es[1024];
    __shared__ float gsum[9];
    __shared__ float w3s[9];

    const int b = blockIdx.x >> 6;
    const int d = blockIdx.x & 63;
    const int tid = threadIdx.x;

    for (int i = tid; i < 1024; i += 256) {
        size_t base = (size_t)(b * NSEQ + i) * OUTF + 3 * CC + d;
        q2s[i] = g_qkv[base];
        k2s[i] = g_qkv[base + DD];
        es[i]  = g_qkv[base + 2 * DD] * ESC_CONST;
    }
    if (tid < 9) gsum[tid] = 0.f;
    __syncthreads();

    float p[9];
#pragma unroll
    for (int j = 0; j < 9; j++) p[j] = 0.f;
    for (int i = tid; i < 1024; i += 256) {
        int y = i >> 5, x = i & 31;
        float e = es[i];
#pragma unroll
        for (int ky = 0; ky < 3; ky++) {
            int yy = y + ky - 1;
            if (yy < 0 || yy > 31) continue;
#pragma unroll
            for (int kx = 0; kx < 3; kx++) {
                int xx = x + kx - 1;
                if (xx >= 0 && xx <= 31) p[ky * 3 + kx] += k2s[yy * 32 + xx] * e;
            }
        }
    }
#pragma unroll
    for (int j = 0; j < 9; j++) {
        float v = p[j];
#pragma unroll
        for (int o = 16; o > 0; o >>= 1) v += __shfl_down_sync(0xffffffffu, v, o);
        if ((tid & 31) == 0) atomicAdd(&gsum[j], v);
    }
    __syncthreads();
    if (tid == 0) {
        float nrm = 0.f;
#pragma unroll
        for (int j = 0; j < 9; j++) nrm += gsum[j] * gsum[j];
        float inv = 1.f / (sqrtf(nrm) + 1.f);
#pragma unroll
        for (int j = 0; j < 9; j++) w3s[j] = w3[d * 9 + j] - gsum[j] * inv;
    }
    __syncthreads();

    for (int i = tid; i < 1024; i += 256) {
        int y = i >> 5, x = i & 31;
        float acc = 0.f;
#pragma unroll
        for (int ky = 0; ky < 3; ky++) {
            int yy = y + ky - 1;
            if (yy < 0 || yy > 31) continue;
#pragma unroll
            for (int kx = 0; kx < 3; kx++) {
                int xx = x + kx - 1;
                if (xx >= 0 && xx <= 31) acc += q2s[yy * 32 + xx] * w3s[ky * 3 + kx];
            }
        }
        g_xcat[(size_t)(b * NSEQ + i) * XCATC + CC + d] = acc;
    }
}

// ---------------------------------------------------------------------------
// Launch: GEMM1 -> (swiglu+x1, dwc+x2) -> GEMM2
// ---------------------------------------------------------------------------
extern "C" void kernel_launch(void* const* d_in, const int* in_sizes, int n_in,
                              void* d_out, int out_size)
{
    const float* x      = (const float*)d_in[0];
    const float* W_qkv  = (const float*)d_in[1];
    const float* b_qkv  = (const float*)d_in[2];
    const float* w1     = (const float*)d_in[3];
    const float* w2     = (const float*)d_in[4];
    const float* w3     = (const float*)d_in[5];
    const float* proj_W = (const float*)d_in[6];
    const float* proj_b = (const float*)d_in[7];
    float* out = (float*)d_out;

    float* qkv = nullptr;
    float* xcat = nullptr;
    cudaGetSymbolAddress((void**)&qkv,  g_qkv);
    cudaGetSymbolAddress((void**)&xcat, g_xcat);

    // GEMM1: qkv = x @ W_qkv + b_qkv   [32768,768]x[768,2496]
    {
        dim3 grid((OUTF + 127) / 128, MROWS / 128);
        gemm_bias_kernel<<<grid, 256>>>(x, W_qkv, b_qkv, qkv, MROWS, OUTF, CC);
    }
    // SwiGLU fast-weight update + x1
    swiglu_x1_kernel<<<BB * HH, 256>>>(w1, w2);
    // DWC fast-weight update + x2
    dwc_x2_kernel<<<BB * DD, 256>>>(w3);
    // GEMM2: out = xcat @ proj_W + proj_b   [32768,832]x[832,768]
    {
        dim3 grid((CC + 127) / 128, MROWS / 128);
        gemm_bias_kernel<<<grid, 256>>>(xcat, proj_W, proj_b, out, MROWS, CC, XCATC);
    }
}

// round 3
// speedup vs baseline: 1.3076x; 1.3076x over previous
#include <cuda_runtime.h>
#include <cuda_bf16.h>
#include <math.h>
#include <stdint.h>

// Problem constants (fixed by the dataset)
#define BB   32
#define NSEQ 1024
#define CC   768
#define HH   12
#define DD   64
#define OUTF 2496            // 3C + 3D
#define XCATC 832            // C + D
#define MROWS (BB*NSEQ)      // 32768

#define ESC_CONST (-(1.0f/1024.0f)*(1.0f/3.0f))

// GEMM tiling
#define MT 128
#define NT 128
#define KC 32
#define SPAD 36              // smem row stride in floats (conflict-free)
#define TILE_F (128 * SPAD)  // floats per tile buffer

// Scratch (device globals -> no allocation)
__device__ float g_qkv[(size_t)MROWS * OUTF];     // [32768, 2496]
__device__ float g_xcat[(size_t)MROWS * XCATC];   // [32768, 832]
__device__ float g_Wt1[(size_t)2560 * CC];        // W_qkv^T padded to 2560 rows
__device__ float g_Wt2[(size_t)CC * XCATC];       // proj_W^T [768, 832]

__device__ __forceinline__ uint32_t f2tf32(float f) {
    uint32_t r;
    asm("cvt.rna.tf32.f32 %0, %1;" : "=r"(r) : "f"(f));
    return r;
}

// ---------------------------------------------------------------------------
// Transpose with row padding: out[n][k] = in[k][n]; zero rows n in [inC, outR)
// ---------------------------------------------------------------------------
__global__ void transpose_pad_kernel(const float* __restrict__ in, float* __restrict__ out,
                                     int inR, int inC, int outR)
{
    __shared__ float t[32][33];
    int kb = blockIdx.y * 32, nb = blockIdx.x * 32;
    int x = threadIdx.x, y = threadIdx.y;
    for (int i = y; i < 32; i += 8) {
        int k = kb + i, n = nb + x;
        t[i][x] = (k < inR && n < inC) ? in[(size_t)k * inC + n] : 0.f;
    }
    __syncthreads();
    for (int i = y; i < 32; i += 8) {
        int n = nb + i, k = kb + x;
        if (n < outR && k < inR) out[(size_t)n * inR + k] = t[x][i];
    }
}

// ---------------------------------------------------------------------------
// TF32 mma.sync GEMM: C[M,Nn] = A[M,K] @ Bt[*,K]^T + bias[Nn]
// A row-major [M,K]; Bt row-major [Npad,K] (i.e. B col-major -> row.col mma).
// 128x128 CTA tile, BK=32, 256 threads, warp tile 64x32 (2x4 warps).
// ---------------------------------------------------------------------------
__device__ __forceinline__ void load_tile_tf32(float* __restrict__ dst,
    const float* __restrict__ src, int ld, int tid)
{
    // 128 rows x 32 cols; 256 threads x 4 float4
#pragma unroll
    for (int t = 0; t < 4; t++) {
        int idx = tid + t * 256;
        int r = idx >> 3, q = (idx & 7) * 4;
        float4 v = *(const float4*)&src[(size_t)r * ld + q];
        uint32_t* d = (uint32_t*)&dst[r * SPAD + q];
        d[0] = f2tf32(v.x); d[1] = f2tf32(v.y);
        d[2] = f2tf32(v.z); d[3] = f2tf32(v.w);
    }
}

__global__ __launch_bounds__(256) void gemm_mma_kernel(
    const float* __restrict__ A, const float* __restrict__ Bt,
    const float* __restrict__ bias, float* __restrict__ C,
    int M, int Nn, int K)
{
    extern __shared__ float sm[];
    float* As[2] = {sm,            sm + 2 * TILE_F};
    float* Bs[2] = {sm + TILE_F,   sm + 3 * TILE_F};

    const int tid = threadIdx.x;
    const int wid = tid >> 5, lane = tid & 31;
    const int g = lane >> 2, tg = lane & 3;
    const int wm = (wid >> 2) * 64;       // warp M offset (0/64)
    const int wn = (wid & 3) * 32;        // warp N offset (0..96)
    const int m0 = blockIdx.y * MT;
    const int n0 = blockIdx.x * NT;
    const int nk = K / KC;

    float acc[4][4][4];
#pragma unroll
    for (int mi = 0; mi < 4; mi++)
#pragma unroll
        for (int nj = 0; nj < 4; nj++)
#pragma unroll
            for (int q = 0; q < 4; q++) acc[mi][nj][q] = 0.f;

    load_tile_tf32(As[0], A + (size_t)m0 * K, K, tid);
    load_tile_tf32(Bs[0], Bt + (size_t)n0 * K, K, tid);
    __syncthreads();

    int buf = 0;
    for (int kt = 0; kt < nk; kt++) {
        if (kt + 1 < nk) {
            load_tile_tf32(As[buf ^ 1], A + (size_t)m0 * K + (kt + 1) * KC, K, tid);
            load_tile_tf32(Bs[buf ^ 1], Bt + (size_t)n0 * K + (kt + 1) * KC, K, tid);
        }
        const float* a_s = As[buf];
        const float* b_s = Bs[buf];
#pragma unroll
        for (int ks = 0; ks < 4; ks++) {
            const int kk = ks * 8;
            uint32_t a[4][4], b[4][2];
#pragma unroll
            for (int mi = 0; mi < 4; mi++) {
                const int row = wm + mi * 16;
                a[mi][0] = *(const uint32_t*)&a_s[(row + g) * SPAD + kk + tg];
                a[mi][1] = *(const uint32_t*)&a_s[(row + g + 8) * SPAD + kk + tg];
                a[mi][2] = *(const uint32_t*)&a_s[(row + g) * SPAD + kk + tg + 4];
                a[mi][3] = *(const uint32_t*)&a_s[(row + g + 8) * SPAD + kk + tg + 4];
            }
#pragma unroll
            for (int nj = 0; nj < 4; nj++) {
                const int col = wn + nj * 8;
                b[nj][0] = *(const uint32_t*)&b_s[(col + g) * SPAD + kk + tg];
                b[nj][1] = *(const uint32_t*)&b_s[(col + g) * SPAD + kk + tg + 4];
            }
#pragma unroll
            for (int mi = 0; mi < 4; mi++)
#pragma unroll
                for (int nj = 0; nj < 4; nj++) {
                    asm volatile(
                        "mma.sync.aligned.m16n8k8.row.col.f32.tf32.tf32.f32 "
                        "{%0,%1,%2,%3}, {%4,%5,%6,%7}, {%8,%9}, {%0,%1,%2,%3};"
                        : "+f"(acc[mi][nj][0]), "+f"(acc[mi][nj][1]),
                          "+f"(acc[mi][nj][2]), "+f"(acc[mi][nj][3])
                        : "r"(a[mi][0]), "r"(a[mi][1]), "r"(a[mi][2]), "r"(a[mi][3]),
                          "r"(b[nj][0]), "r"(b[nj][1]));
                }
        }
        __syncthreads();
        buf ^= 1;
    }

    // epilogue: d0,d1 -> (row, col..col+1); d2,d3 -> (row+8, col..col+1)
#pragma unroll
    for (int nj = 0; nj < 4; nj++) {
        const int gc = n0 + wn + nj * 8 + tg * 2;
        if (gc >= Nn) continue;
        const float bx = bias[gc], by = bias[gc + 1];
#pragma unroll
        for (int mi = 0; mi < 4; mi++) {
            const int row = m0 + wm + mi * 16 + g;
            float2 s0 = make_float2(acc[mi][nj][0] + bx, acc[mi][nj][1] + by);
            float2 s1 = make_float2(acc[mi][nj][2] + bx, acc[mi][nj][3] + by);
            *(float2*)&C[(size_t)row * Nn + gc] = s0;
            *(float2*)&C[(size_t)(row + 8) * Nn + gc] = s1;
        }
    }
}

// ---------------------------------------------------------------------------
// Fused per-(b,h) SwiGLU fast-weight update + x1 apply.
// ---------------------------------------------------------------------------
__global__ __launch_bounds__(256) void swiglu_x1_kernel(
    const float* __restrict__ w1, const float* __restrict__ w2)
{
    __shared__ __align__(16) float w1s[DD * DD];
    __shared__ __align__(16) float w2s[DD * DD];
    __shared__ __align__(16) float ks[16 * DD];
    __shared__ __align__(16) float eas[16 * DD];
    __shared__ __align__(16) float egs[16 * DD];
    __shared__ float colsum[2 * DD];

    const int b = blockIdx.x / HH;
    const int h = blockIdx.x % HH;
    const int tid = threadIdx.x;
    const int d0 = (tid >> 4) << 2;
    const int e0 = (tid & 15) << 2;
    const int zrow = tid >> 4;

    for (int i = tid; i < DD * DD; i += 256) {
        w1s[i] = w1[h * DD * DD + i];
        w2s[i] = w2[h * DD * DD + i];
    }
    if (tid < 2 * DD) colsum[tid] = 0.f;

    float g1[4][4], g2[4][4];
#pragma unroll
    for (int i = 0; i < 4; i++)
#pragma unroll
        for (int j = 0; j < 4; j++) { g1[i][j] = 0.f; g2[i][j] = 0.f; }

    __syncthreads();

    for (int n0 = 0; n0 < NSEQ; n0 += 16) {
        for (int i = tid; i < 16 * DD; i += 256) {
            int n = i >> 6, d = i & 63;
            ks[i] = g_qkv[(size_t)(b * NSEQ + n0 + n) * OUTF + CC + h * DD + d];
        }
        __syncthreads();

        float z1[4] = {0.f, 0.f, 0.f, 0.f}, z2[4] = {0.f, 0.f, 0.f, 0.f};
        const float* krow = ks + zrow * DD;
#pragma unroll 16
        for (int d = 0; d < DD; d++) {
            float kv = krow[d];
            float4 w1v = *(const float4*)&w1s[d * DD + e0];
            float4 w2v = *(const float4*)&w2s[d * DD + e0];
            z1[0] += kv * w1v.x; z1[1] += kv * w1v.y; z1[2] += kv * w1v.z; z1[3] += kv * w1v.w;
            z2[0] += kv * w2v.x; z2[1] += kv * w2v.y; z2[2] += kv * w2v.z; z2[3] += kv * w2v.w;
        }
        float4 vv = *(const float4*)&g_qkv[(size_t)(b * NSEQ + n0 + zrow) * OUTF + 2 * CC + h * DD + e0];
        float vj[4] = {vv.x, vv.y, vv.z, vv.w};
        float4 eav, egv;
        float* eap = (float*)&eav; float* egp = (float*)&egv;
#pragma unroll
        for (int j = 0; j < 4; j++) {
            float ev = ESC_CONST * vj[j];
            float s = 1.f / (1.f + expf(-z2[j]));
            float a = z2[j] * s;
            eap[j] = ev * a;
            egp[j] = ev * z1[j] * (s * (1.f + z2[j] * (1.f - s)));
        }
        *(float4*)&eas[zrow * DD + e0] = eav;
        *(float4*)&egs[zrow * DD + e0] = egv;
        __syncthreads();

#pragma unroll
        for (int nn = 0; nn < 16; nn++) {
            float4 ka = *(const float4*)&ks[nn * DD + d0];
            float4 ea = *(const float4*)&eas[nn * DD + e0];
            float4 eg = *(const float4*)&egs[nn * DD + e0];
            float kr[4] = {ka.x, ka.y, ka.z, ka.w};
            float er[4] = {ea.x, ea.y, ea.z, ea.w};
            float gr[4] = {eg.x, eg.y, eg.z, eg.w};
#pragma unroll
            for (int i = 0; i < 4; i++)
#pragma unroll
                for (int j = 0; j < 4; j++) {
                    g1[i][j] += kr[i] * er[j];
                    g2[i][j] += kr[i] * gr[j];
                }
        }
        __syncthreads();
    }

#pragma unroll
    for (int j = 0; j < 4; j++) {
        float s1 = 0.f, s2 = 0.f;
#pragma unroll
        for (int i = 0; i < 4; i++) { s1 += g1[i][j] * g1[i][j]; s2 += g2[i][j] * g2[i][j]; }
        atomicAdd(&colsum[e0 + j], s1);
        atomicAdd(&colsum[DD + e0 + j], s2);
    }
    __syncthreads();

#pragma unroll
    for (int j = 0; j < 4; j++) {
        float inv1 = 1.f / (sqrtf(colsum[e0 + j]) + 1.f);
        float inv2 = 1.f / (sqrtf(colsum[DD + e0 + j]) + 1.f);
#pragma unroll
        for (int i = 0; i < 4; i++) {
            w1s[(d0 + i) * DD + e0 + j] -= g1[i][j] * inv1;
            w2s[(d0 + i) * DD + e0 + j] -= g2[i][j] * inv2;
        }
    }
    __syncthreads();

    for (int n0 = 0; n0 < NSEQ; n0 += 16) {
        for (int i = tid; i < 16 * DD; i += 256) {
            int n = i >> 6, d = i & 63;
            ks[i] = g_qkv[(size_t)(b * NSEQ + n0 + n) * OUTF + h * DD + d];
        }
        __syncthreads();
        float y1[4] = {0.f, 0.f, 0.f, 0.f}, y2[4] = {0.f, 0.f, 0.f, 0.f};
        const float* qrow = ks + zrow * DD;
#pragma unroll 16
        for (int d = 0; d < DD; d++) {
            float qv = qrow[d];
            float4 w1v = *(const float4*)&w1s[d * DD + e0];
            float4 w2v = *(const float4*)&w2s[d * DD + e0];
            y1[0] += qv * w1v.x; y1[1] += qv * w1v.y; y1[2] += qv * w1v.z; y1[3] += qv * w1v.w;
            y2[0] += qv * w2v.x; y2[1] += qv * w2v.y; y2[2] += qv * w2v.z; y2[3] += qv * w2v.w;
        }
        float4 o;
        float* op = (float*)&o;
#pragma unroll
        for (int j = 0; j < 4; j++) {
            float s = 1.f / (1.f + expf(-y2[j]));
            op[j] = y1[j] * (y2[j] * s);
        }
        *(float4*)&g_xcat[(size_t)(b * NSEQ + n0 + zrow) * XCATC + h * DD + e0] = o;
        __syncthreads();
    }
}

// ---------------------------------------------------------------------------
// Fused per-(b,d) depthwise-conv fast-weight update + conv apply.
// ---------------------------------------------------------------------------
__global__ __launch_bounds__(256) void dwc_x2_kernel(const float* __restrict__ w3)
{
    __shared__ float q2s[1024], k2s[1024], es[1024];
    __shared__ float gsum[9];
    __shared__ float w3s[9];

    const int b = blockIdx.x >> 6;
    const int d = blockIdx.x & 63;
    const int tid = threadIdx.x;

    for (int i = tid; i < 1024; i += 256) {
        size_t base = (size_t)(b * NSEQ + i) * OUTF + 3 * CC + d;
        q2s[i] = g_qkv[base];
        k2s[i] = g_qkv[base + DD];
        es[i]  = g_qkv[base + 2 * DD] * ESC_CONST;
    }
    if (tid < 9) gsum[tid] = 0.f;
    __syncthreads();

    float p[9];
#pragma unroll
    for (int j = 0; j < 9; j++) p[j] = 0.f;
    for (int i = tid; i < 1024; i += 256) {
        int y = i >> 5, x = i & 31;
        float e = es[i];
#pragma unroll
        for (int ky = 0; ky < 3; ky++) {
            int yy = y + ky - 1;
            if (yy < 0 || yy > 31) continue;
#pragma unroll
            for (int kx = 0; kx < 3; kx++) {
                int xx = x + kx - 1;
                if (xx >= 0 && xx <= 31) p[ky * 3 + kx] += k2s[yy * 32 + xx] * e;
            }
        }
    }
#pragma unroll
    for (int j = 0; j < 9; j++) {
        float v = p[j];
#pragma unroll
        for (int o = 16; o > 0; o >>= 1) v += __shfl_down_sync(0xffffffffu, v, o);
        if ((tid & 31) == 0) atomicAdd(&gsum[j], v);
    }
    __syncthreads();
    if (tid == 0) {
        float nrm = 0.f;
#pragma unroll
        for (int j = 0; j < 9; j++) nrm += gsum[j] * gsum[j];
        float inv = 1.f / (sqrtf(nrm) + 1.f);
#pragma unroll
        for (int j = 0; j < 9; j++) w3s[j] = w3[d * 9 + j] - gsum[j] * inv;
    }
    __syncthreads();

    for (int i = tid; i < 1024; i += 256) {
        int y = i >> 5, x = i & 31;
        float acc = 0.f;
#pragma unroll
        for (int ky = 0; ky < 3; ky++) {
            int yy = y + ky - 1;
            if (yy < 0 || yy > 31) continue;
#pragma unroll
            for (int kx = 0; kx < 3; kx++) {
                int xx = x + kx - 1;
                if (xx >= 0 && xx <= 31) acc += q2s[yy * 32 + xx] * w3s[ky * 3 + kx];
            }
        }
        g_xcat[(size_t)(b * NSEQ + i) * XCATC + CC + d] = acc;
    }
}

// ---------------------------------------------------------------------------
// Launch
// ---------------------------------------------------------------------------
extern "C" void kernel_launch(void* const* d_in, const int* in_sizes, int n_in,
                              void* d_out, int out_size)
{
    const float* x      = (const float*)d_in[0];
    const float* W_qkv  = (const float*)d_in[1];
    const float* b_qkv  = (const float*)d_in[2];
    const float* w1     = (const float*)d_in[3];
    const float* w2     = (const float*)d_in[4];
    const float* w3     = (const float*)d_in[5];
    const float* proj_W = (const float*)d_in[6];
    const float* proj_b = (const float*)d_in[7];
    float* out = (float*)d_out;

    float *qkv, *xcat, *Wt1, *Wt2;
    cudaGetSymbolAddress((void**)&qkv,  g_qkv);
    cudaGetSymbolAddress((void**)&xcat, g_xcat);
    cudaGetSymbolAddress((void**)&Wt1,  g_Wt1);
    cudaGetSymbolAddress((void**)&Wt2,  g_Wt2);

    const int SMEM_BYTES = 4 * TILE_F * 4;  // 73728
    cudaFuncSetAttribute(gemm_mma_kernel, cudaFuncAttributeMaxDynamicSharedMemorySize, SMEM_BYTES);

    // Transposes: Wt1[n][k] = W_qkv[k][n] (pad to 2560 rows); Wt2[n][k] = proj_W[k][n]
    {
        dim3 blk(32, 8);
        transpose_pad_kernel<<<dim3(2560 / 32, CC / 32), blk>>>(W_qkv, Wt1, CC, OUTF, 2560);
        transpose_pad_kernel<<<dim3(CC / 32, XCATC / 32), blk>>>(proj_W, Wt2, XCATC, CC, CC);
    }
    // GEMM1: qkv = x @ W_qkv + b_qkv   [32768,768] x [768,2496]
    {
        dim3 grid(2560 / NT, MROWS / MT);
        gemm_mma_kernel<<<grid, 256, SMEM_BYTES>>>(x, Wt1, b_qkv, qkv, MROWS, OUTF, CC);
    }
    // SwiGLU fast-weight update + x1
    swiglu_x1_kernel<<<BB * HH, 256>>>(w1, w2);
    // DWC fast-weight update + x2
    dwc_x2_kernel<<<BB * DD, 256>>>(w3);
    // GEMM2: out = xcat @ proj_W + proj_b   [32768,832] x [832,768]
    {
        dim3 grid(CC / NT, MROWS / MT);
        gemm_mma_kernel<<<grid, 256, SMEM_BYTES>>>(xcat, Wt2, proj_b, out, MROWS, CC, XCATC);
    }
}

// round 4
// speedup vs baseline: 2.4433x; 1.8685x over previous
#include <cuda_runtime.h>
#include <cuda_bf16.h>
#include <math.h>
#include <stdint.h>

// Problem constants (fixed by the dataset)
#define BB   32
#define NSEQ 1024
#define CC   768
#define HH   12
#define DD   64
#define OUTF 2496            // 3C + 3D
#define XCATC 832            // C + D
#define MROWS (BB*NSEQ)      // 32768

#define ESC_CONST (-(1.0f/1024.0f)*(1.0f/3.0f))

// GEMM tiling
#define MT 128
#define NT 128
#define KC 32
#define STAGE_F (128 * 32)           // floats per (A or B) tile
#define STAGE_BYTES (2 * STAGE_F * 4) // 32768 bytes per stage (A+B)

// Scratch (device globals -> no allocation)
__device__ float g_qkv[(size_t)MROWS * OUTF];     // [32768, 2496]
__device__ float g_xcat[(size_t)MROWS * XCATC];   // [32768, 832]
__device__ float g_Wt1[(size_t)2560 * CC];        // W_qkv^T padded to 2560 rows
__device__ float g_Wt2[(size_t)CC * XCATC];       // proj_W^T [768, 832]

__device__ __forceinline__ uint32_t smem_u32(const void* p) {
    uint32_t a;
    asm("{ .reg .u64 t; cvta.to.shared.u64 t, %1; cvt.u32.u64 %0, t; }" : "=r"(a) : "l"(p));
    return a;
}
__device__ __forceinline__ void cp16(uint32_t dst, const void* src) {
    asm volatile("cp.async.cg.shared.global [%0], [%1], 16;" :: "r"(dst), "l"(src));
}
#define CP_COMMIT() asm volatile("cp.async.commit_group;" ::: "memory")
#define CP_WAIT1()  asm volatile("cp.async.wait_group 1;" ::: "memory")

// swizzled smem read: row r (stride 32 floats), col c; groups of 4 XORed by r&7
__device__ __forceinline__ float ldsw(const float* s, int r, int c) {
    return s[r * 32 + ((((c >> 2) ^ (r & 7)) << 2) | (c & 3))];
}

// ---------------------------------------------------------------------------
// Transpose with row padding: out[n][k] = in[k][n]; zero rows n in [inC, outR)
// ---------------------------------------------------------------------------
__global__ void transpose_pad_kernel(const float* __restrict__ in, float* __restrict__ out,
                                     int inR, int inC, int outR)
{
    __shared__ float t[32][33];
    int kb = blockIdx.y * 32, nb = blockIdx.x * 32;
    int x = threadIdx.x, y = threadIdx.y;
    for (int i = y; i < 32; i += 8) {
        int k = kb + i, n = nb + x;
        t[i][x] = (k < inR && n < inC) ? in[(size_t)k * inC + n] : 0.f;
    }
    __syncthreads();
    for (int i = y; i < 32; i += 8) {
        int n = nb + i, k = kb + x;
        if (n < outR && k < inR) out[(size_t)n * inR + k] = t[x][i];
    }
}

// ---------------------------------------------------------------------------
// TF32 mma.sync GEMM with cp.async 3-stage pipeline.
// C[M,Nn] = A[M,K] @ Bt[*,K]^T + bias[Nn]
// A row-major [M,K]; Bt row-major [Npad,K]. 128x128 CTA tile, BK=32, 256 thr.
// Note: fp32 bits fed directly to tf32 mma (HW truncation of low mantissa).
// ---------------------------------------------------------------------------
__device__ __forceinline__ void fill_stage(uint32_t sbase,
    const float* __restrict__ A, const float* __restrict__ Bt,
    int m0, int n0, int K, int k0, int tid)
{
    const float* Ab = A + (size_t)m0 * K + k0;
#pragma unroll
    for (int i = 0; i < 4; i++) {
        int idx = tid + i * 256;
        int r = idx >> 3, q = idx & 7;
        uint32_t off = (uint32_t)(r * 128 + ((q ^ (r & 7)) * 16));
        cp16(sbase + off, Ab + (size_t)r * K + q * 4);
    }
    const float* Bb = Bt + (size_t)n0 * K + k0;
#pragma unroll
    for (int i = 0; i < 4; i++) {
        int idx = tid + i * 256;
        int r = idx >> 3, q = idx & 7;
        uint32_t off = (uint32_t)(r * 128 + ((q ^ (r & 7)) * 16));
        cp16(sbase + (uint32_t)STAGE_F * 4 + off, Bb + (size_t)r * K + q * 4);
    }
}

__global__ __launch_bounds__(256) void gemm_mma_kernel(
    const float* __restrict__ A, const float* __restrict__ Bt,
    const float* __restrict__ bias, float* __restrict__ C,
    int M, int Nn, int K)
{
    extern __shared__ float sm[];
    const uint32_t sb = smem_u32(sm);

    const int tid = threadIdx.x;
    const int wid = tid >> 5, lane = tid & 31;
    const int g = lane >> 2, tg = lane & 3;
    const int wm = (wid >> 2) * 64;       // warp M offset (0/64)
    const int wn = (wid & 3) * 32;        // warp N offset (0..96)
    const int m0 = blockIdx.y * MT;
    const int n0 = blockIdx.x * NT;
    const int nk = K / KC;

    float acc[4][4][4];
#pragma unroll
    for (int mi = 0; mi < 4; mi++)
#pragma unroll
        for (int nj = 0; nj < 4; nj++)
#pragma unroll
            for (int q = 0; q < 4; q++) acc[mi][nj][q] = 0.f;

    // prologue: fill stages 0 and 1
    fill_stage(sb, A, Bt, m0, n0, K, 0, tid);
    CP_COMMIT();
    fill_stage(sb + STAGE_BYTES, A, Bt, m0, n0, K, KC, tid);
    CP_COMMIT();

    for (int kt = 0; kt < nk; kt++) {
        CP_WAIT1();           // stage kt's group complete (<=1 newer pending)
        __syncthreads();      // data visible + prior reads of recycled stage done
        if (kt + 2 < nk)
            fill_stage(sb + (uint32_t)((kt + 2) % 3) * STAGE_BYTES,
                       A, Bt, m0, n0, K, (kt + 2) * KC, tid);
        CP_COMMIT();          // exactly one group per iteration (may be empty)

        const float* a_s = sm + (size_t)(kt % 3) * (2 * STAGE_F);
        const float* b_s = a_s + STAGE_F;
#pragma unroll
        for (int ks = 0; ks < 4; ks++) {
            const int kk = ks * 8;
            uint32_t a[4][4], b[4][2];
#pragma unroll
            for (int mi = 0; mi < 4; mi++) {
                const int row = wm + mi * 16;
                a[mi][0] = __float_as_uint(ldsw(a_s, row + g,     kk + tg));
                a[mi][1] = __float_as_uint(ldsw(a_s, row + g + 8, kk + tg));
                a[mi][2] = __float_as_uint(ldsw(a_s, row + g,     kk + tg + 4));
                a[mi][3] = __float_as_uint(ldsw(a_s, row + g + 8, kk + tg + 4));
            }
#pragma unroll
            for (int nj = 0; nj < 4; nj++) {
                const int col = wn + nj * 8;
                b[nj][0] = __float_as_uint(ldsw(b_s, col + g, kk + tg));
                b[nj][1] = __float_as_uint(ldsw(b_s, col + g, kk + tg + 4));
            }
#pragma unroll
            for (int mi = 0; mi < 4; mi++)
#pragma unroll
                for (int nj = 0; nj < 4; nj++) {
                    asm volatile(
                        "mma.sync.aligned.m16n8k8.row.col.f32.tf32.tf32.f32 "
                        "{%0,%1,%2,%3}, {%4,%5,%6,%7}, {%8,%9}, {%0,%1,%2,%3};"
                        : "+f"(acc[mi][nj][0]), "+f"(acc[mi][nj][1]),
                          "+f"(acc[mi][nj][2]), "+f"(acc[mi][nj][3])
                        : "r"(a[mi][0]), "r"(a[mi][1]), "r"(a[mi][2]), "r"(a[mi][3]),
                          "r"(b[nj][0]), "r"(b[nj][1]));
                }
        }
        __syncthreads();
    }

    // epilogue
#pragma unroll
    for (int nj = 0; nj < 4; nj++) {
        const int gc = n0 + wn + nj * 8 + tg * 2;
        if (gc >= Nn) continue;
        const float bx = bias[gc], by = bias[gc + 1];
#pragma unroll
        for (int mi = 0; mi < 4; mi++) {
            const int row = m0 + wm + mi * 16 + g;
            float2 s0 = make_float2(acc[mi][nj][0] + bx, acc[mi][nj][1] + by);
            float2 s1 = make_float2(acc[mi][nj][2] + bx, acc[mi][nj][3] + by);
            *(float2*)&C[(size_t)row * Nn + gc] = s0;
            *(float2*)&C[(size_t)(row + 8) * Nn + gc] = s1;
        }
    }
}

// ---------------------------------------------------------------------------
// Fused per-(b,h) SwiGLU fast-weight update + x1 apply. 32-row tiles:
// each thread handles rows {zr, zr+16} per weight-fragment load (halves
// w1s/w2s crossbar traffic per output vs 16-row tiles).
// ---------------------------------------------------------------------------
__global__ __launch_bounds__(256) void swiglu_x1_kernel(
    const float* __restrict__ w1, const float* __restrict__ w2)
{
    __shared__ __align__(16) float w1s[DD * DD];
    __shared__ __align__(16) float w2s[DD * DD];
    __shared__ __align__(16) float ks[32 * DD];
    __shared__ __align__(16) float eas[32 * DD];
    __shared__ __align__(16) float egs[32 * DD];
    __shared__ float colsum[2 * DD];

    const int b = blockIdx.x / HH;
    const int h = blockIdx.x % HH;
    const int tid = threadIdx.x;
    const int d0 = (tid >> 4) << 2;
    const int e0 = (tid & 15) << 2;
    const int zr = tid >> 4;          // rows zr and zr+16

    for (int i = tid; i < DD * DD; i += 256) {
        w1s[i] = w1[h * DD * DD + i];
        w2s[i] = w2[h * DD * DD + i];
    }
    if (tid < 2 * DD) colsum[tid] = 0.f;

    float g1[4][4], g2[4][4];
#pragma unroll
    for (int i = 0; i < 4; i++)
#pragma unroll
        for (int j = 0; j < 4; j++) { g1[i][j] = 0.f; g2[i][j] = 0.f; }

    __syncthreads();

    for (int n0 = 0; n0 < NSEQ; n0 += 32) {
        // load k tile [32,64] (2 float4 per thread, coalesced)
#pragma unroll
        for (int j = 0; j < 2; j++) {
            int idx = tid + j * 256;
            int row = idx >> 4, c4 = (idx & 15) << 2;
            *(float4*)&ks[row * DD + c4] =
                *(const float4*)&g_qkv[(size_t)(b * NSEQ + n0 + row) * OUTF + CC + h * DD + c4];
        }
        __syncthreads();

        float z1a[4] = {0,0,0,0}, z2a[4] = {0,0,0,0};
        float z1b[4] = {0,0,0,0}, z2b[4] = {0,0,0,0};
        const float* kr0 = ks + zr * DD;
        const float* kr1 = ks + (zr + 16) * DD;
#pragma unroll 16
        for (int d = 0; d < DD; d++) {
            float ka = kr0[d], kb = kr1[d];
            float4 w1v = *(const float4*)&w1s[d * DD + e0];
            float4 w2v = *(const float4*)&w2s[d * DD + e0];
            z1a[0] += ka * w1v.x; z1a[1] += ka * w1v.y; z1a[2] += ka * w1v.z; z1a[3] += ka * w1v.w;
            z2a[0] += ka * w2v.x; z2a[1] += ka * w2v.y; z2a[2] += ka * w2v.z; z2a[3] += ka * w2v.w;
            z1b[0] += kb * w1v.x; z1b[1] += kb * w1v.y; z1b[2] += kb * w1v.z; z1b[3] += kb * w1v.w;
            z2b[0] += kb * w2v.x; z2b[1] += kb * w2v.y; z2b[2] += kb * w2v.z; z2b[3] += kb * w2v.w;
        }
        float4 va = *(const float4*)&g_qkv[(size_t)(b * NSEQ + n0 + zr) * OUTF + 2 * CC + h * DD + e0];
        float4 vb = *(const float4*)&g_qkv[(size_t)(b * NSEQ + n0 + zr + 16) * OUTF + 2 * CC + h * DD + e0];
        float4 eava, egva, eavb, egvb;
        {
            float* vp = (float*)&va; float* ep = (float*)&eava; float* gp = (float*)&egva;
#pragma unroll
            for (int j = 0; j < 4; j++) {
                float ev = ESC_CONST * vp[j];
                float s = 1.f / (1.f + __expf(-z2a[j]));
                ep[j] = ev * (z2a[j] * s);
                gp[j] = ev * z1a[j] * (s * (1.f + z2a[j] * (1.f - s)));
            }
            vp = (float*)&vb; ep = (float*)&eavb; gp = (float*)&egvb;
#pragma unroll
            for (int j = 0; j < 4; j++) {
                float ev = ESC_CONST * vp[j];
                float s = 1.f / (1.f + __expf(-z2b[j]));
                ep[j] = ev * (z2b[j] * s);
                gp[j] = ev * z1b[j] * (s * (1.f + z2b[j] * (1.f - s)));
            }
        }
        *(float4*)&eas[zr * DD + e0] = eava;
        *(float4*)&egs[zr * DD + e0] = egva;
        *(float4*)&eas[(zr + 16) * DD + e0] = eavb;
        *(float4*)&egs[(zr + 16) * DD + e0] = egvb;
        __syncthreads();

#pragma unroll
        for (int nn = 0; nn < 32; nn++) {
            float4 ka4 = *(const float4*)&ks[nn * DD + d0];
            float4 ea4 = *(const float4*)&eas[nn * DD + e0];
            float4 eg4 = *(const float4*)&egs[nn * DD + e0];
            float kr[4] = {ka4.x, ka4.y, ka4.z, ka4.w};
            float er[4] = {ea4.x, ea4.y, ea4.z, ea4.w};
            float gr[4] = {eg4.x, eg4.y, eg4.z, eg4.w};
#pragma unroll
            for (int i = 0; i < 4; i++)
#pragma unroll
                for (int j = 0; j < 4; j++) {
                    g1[i][j] += kr[i] * er[j];
                    g2[i][j] += kr[i] * gr[j];
                }
        }
        __syncthreads();
    }

    // column norms
#pragma unroll
    for (int j = 0; j < 4; j++) {
        float s1 = 0.f, s2 = 0.f;
#pragma unroll
        for (int i = 0; i < 4; i++) { s1 += g1[i][j] * g1[i][j]; s2 += g2[i][j] * g2[i][j]; }
        atomicAdd(&colsum[e0 + j], s1);
        atomicAdd(&colsum[DD + e0 + j], s2);
    }
    __syncthreads();

#pragma unroll
    for (int j = 0; j < 4; j++) {
        float inv1 = 1.f / (sqrtf(colsum[e0 + j]) + 1.f);
        float inv2 = 1.f / (sqrtf(colsum[DD + e0 + j]) + 1.f);
#pragma unroll
        for (int i = 0; i < 4; i++) {
            w1s[(d0 + i) * DD + e0 + j] -= g1[i][j] * inv1;
            w2s[(d0 + i) * DD + e0 + j] -= g2[i][j] * inv2;
        }
    }
    __syncthreads();

    // phase 3: x1 = (q@w1u) * silu(q@w2u), 32-row tiles
    for (int n0 = 0; n0 < NSEQ; n0 += 32) {
#pragma unroll
        for (int j = 0; j < 2; j++) {
            int idx = tid + j * 256;
            int row = idx >> 4, c4 = (idx & 15) << 2;
            *(float4*)&ks[row * DD + c4] =
                *(const float4*)&g_qkv[(size_t)(b * NSEQ + n0 + row) * OUTF + h * DD + c4];
        }
        __syncthreads();
        float y1a[4] = {0,0,0,0}, y2a[4] = {0,0,0,0};
        float y1b[4] = {0,0,0,0}, y2b[4] = {0,0,0,0};
        const float* qr0 = ks + zr * DD;
        const float* qr1 = ks + (zr + 16) * DD;
#pragma unroll 16
        for (int d = 0; d < DD; d++) {
            float qa = qr0[d], qb = qr1[d];
            float4 w1v = *(const float4*)&w1s[d * DD + e0];
            float4 w2v = *(const float4*)&w2s[d * DD + e0];
            y1a[0] += qa * w1v.x; y1a[1] += qa * w1v.y; y1a[2] += qa * w1v.z; y1a[3] += qa * w1v.w;
            y2a[0] += qa * w2v.x; y2a[1] += qa * w2v.y; y2a[2] += qa * w2v.z; y2a[3] += qa * w2v.w;
            y1b[0] += qb * w1v.x; y1b[1] += qb * w1v.y; y1b[2] += qb * w1v.z; y1b[3] += qb * w1v.w;
            y2b[0] += qb * w2v.x; y2b[1] += qb * w2v.y; y2b[2] += qb * w2v.z; y2b[3] += qb * w2v.w;
        }
        float4 oa, ob;
        float* oap = (float*)&oa; float* obp = (float*)&ob;
#pragma unroll
        for (int j = 0; j < 4; j++) {
            float s = 1.f / (1.f + __expf(-y2a[j]));
            oap[j] = y1a[j] * (y2a[j] * s);
            s = 1.f / (1.f + __expf(-y2b[j]));
            obp[j] = y1b[j] * (y2b[j] * s);
        }
        *(float4*)&g_xcat[(size_t)(b * NSEQ + n0 + zr) * XCATC + h * DD + e0] = oa;
        *(float4*)&g_xcat[(size_t)(b * NSEQ + n0 + zr + 16) * XCATC + h * DD + e0] = ob;
        __syncthreads();
    }
}

// ---------------------------------------------------------------------------
// Fused per-(b,d) depthwise-conv fast-weight update + conv apply.
// ---------------------------------------------------------------------------
__global__ __launch_bounds__(256) void dwc_x2_kernel(const float* __restrict__ w3)
{
    __shared__ float q2s[1024], k2s[1024], es[1024];
    __shared__ float gsum[9];
    __shared__ float w3s[9];

    const int b = blockIdx.x >> 6;
    const int d = blockIdx.x & 63;
    const int tid = threadIdx.x;

    for (int i = tid; i < 1024; i += 256) {
        size_t base = (size_t)(b * NSEQ + i) * OUTF + 3 * CC + d;
        q2s[i] = g_qkv[base];
        k2s[i] = g_qkv[base + DD];
        es[i]  = g_qkv[base + 2 * DD] * ESC_CONST;
    }
    if (tid < 9) gsum[tid] = 0.f;
    __syncthreads();

    float p[9];
#pragma unroll
    for (int j = 0; j < 9; j++) p[j] = 0.f;
    for (int i = tid; i < 1024; i += 256) {
        int y = i >> 5, x = i & 31;
        float e = es[i];
#pragma unroll
        for (int ky = 0; ky < 3; ky++) {
            int yy = y + ky - 1;
            if (yy < 0 || yy > 31) continue;
#pragma unroll
            for (int kx = 0; kx < 3; kx++) {
                int xx = x + kx - 1;
                if (xx >= 0 && xx <= 31) p[ky * 3 + kx] += k2s[yy * 32 + xx] * e;
            }
        }
    }
#pragma unroll
    for (int j = 0; j < 9; j++) {
        float v = p[j];
#pragma unroll
        for (int o = 16; o > 0; o >>= 1) v += __shfl_down_sync(0xffffffffu, v, o);
        if ((tid & 31) == 0) atomicAdd(&gsum[j], v);
    }
    __syncthreads();
    if (tid == 0) {
        float nrm = 0.f;
#pragma unroll
        for (int j = 0; j < 9; j++) nrm += gsum[j] * gsum[j];
        float inv = 1.f / (sqrtf(nrm) + 1.f);
#pragma unroll
        for (int j = 0; j < 9; j++) w3s[j] = w3[d * 9 + j] - gsum[j] * inv;
    }
    __syncthreads();

    for (int i = tid; i < 1024; i += 256) {
        int y = i >> 5, x = i & 31;
        float acc = 0.f;
#pragma unroll
        for (int ky = 0; ky < 3; ky++) {
            int yy = y + ky - 1;
            if (yy < 0 || yy > 31) continue;
#pragma unroll
            for (int kx = 0; kx < 3; kx++) {
                int xx = x + kx - 1;
                if (xx >= 0 && xx <= 31) acc += q2s[yy * 32 + xx] * w3s[ky * 3 + kx];
            }
        }
        g_xcat[(size_t)(b * NSEQ + i) * XCATC + CC + d] = acc;
    }
}

// ---------------------------------------------------------------------------
// Launch
// ---------------------------------------------------------------------------
extern "C" void kernel_launch(void* const* d_in, const int* in_sizes, int n_in,
                              void* d_out, int out_size)
{
    const float* x      = (const float*)d_in[0];
    const float* W_qkv  = (const float*)d_in[1];
    const float* b_qkv  = (const float*)d_in[2];
    const float* w1     = (const float*)d_in[3];
    const float* w2     = (const float*)d_in[4];
    const float* w3     = (const float*)d_in[5];
    const float* proj_W = (const float*)d_in[6];
    const float* proj_b = (const float*)d_in[7];
    float* out = (float*)d_out;

    float *qkv, *xcat, *Wt1, *Wt2;
    cudaGetSymbolAddress((void**)&qkv,  g_qkv);
    cudaGetSymbolAddress((void**)&xcat, g_xcat);
    cudaGetSymbolAddress((void**)&Wt1,  g_Wt1);
    cudaGetSymbolAddress((void**)&Wt2,  g_Wt2);

    const int SMEM_BYTES = 3 * STAGE_BYTES;  // 98304
    cudaFuncSetAttribute(gemm_mma_kernel, cudaFuncAttributeMaxDynamicSharedMemorySize, SMEM_BYTES);

    // Transposes: Wt1[n][k] = W_qkv[k][n] (pad to 2560 rows); Wt2[n][k] = proj_W[k][n]
    {
        dim3 blk(32, 8);
        transpose_pad_kernel<<<dim3(2560 / 32, CC / 32), blk>>>(W_qkv, Wt1, CC, OUTF, 2560);
        transpose_pad_kernel<<<dim3(CC / 32, XCATC / 32), blk>>>(proj_W, Wt2, XCATC, CC, CC);
    }
    // GEMM1: qkv = x @ W_qkv + b_qkv   [32768,768] x [768,2496]
    {
        dim3 grid(2560 / NT, MROWS / MT);
        gemm_mma_kernel<<<grid, 256, SMEM_BYTES>>>(x, Wt1, b_qkv, qkv, MROWS, OUTF, CC);
    }
    // SwiGLU fast-weight update + x1
    swiglu_x1_kernel<<<BB * HH, 256>>>(w1, w2);
    // DWC fast-weight update + x2
    dwc_x2_kernel<<<BB * DD, 256>>>(w3);
    // GEMM2: out = xcat @ proj_W + proj_b   [32768,832] x [832,768]
    {
        dim3 grid(CC / NT, MROWS / MT);
        gemm_mma_kernel<<<grid, 256, SMEM_BYTES>>>(xcat, Wt2, proj_b, out, MROWS, CC, XCATC);
    }
}

// round 5
// speedup vs baseline: 2.9406x; 1.2035x over previous
#include <cuda_runtime.h>
#include <cuda_bf16.h>
#include <math.h>
#include <stdint.h>

// Problem constants (fixed by the dataset)
#define BB   32
#define NSEQ 1024
#define CC   768
#define HH   12
#define DD   64
#define OUTF 2496            // 3C + 3D
#define XCATC 832            // C + D
#define MROWS (BB*NSEQ)      // 32768

#define ESC_CONST (-(1.0f/1024.0f)*(1.0f/3.0f))

// GEMM tiling
#define MT 128
#define NT 128
#define KC 32
#define STAGE_F (128 * 32)            // floats per (A or B) tile
#define STAGE_BYTES (2 * STAGE_F * 4) // 32768 bytes per stage (A+B)

// Scratch (device globals -> no allocation)
__device__ float g_qkv[(size_t)MROWS * OUTF];     // [32768, 2496]
__device__ float g_xcat[(size_t)MROWS * XCATC];   // [32768, 832]
__device__ float g_Wt1[(size_t)2560 * CC];        // W_qkv^T padded to 2560 rows
__device__ float g_Wt2[(size_t)CC * XCATC];       // proj_W^T [768, 832]

__device__ __forceinline__ uint32_t smem_u32(const void* p) {
    uint32_t a;
    asm("{ .reg .u64 t; cvta.to.shared.u64 t, %1; cvt.u32.u64 %0, t; }" : "=r"(a) : "l"(p));
    return a;
}
__device__ __forceinline__ void cp16(uint32_t dst, const void* src) {
    asm volatile("cp.async.cg.shared.global [%0], [%1], 16;" :: "r"(dst), "l"(src));
}
#define CP_COMMIT() asm volatile("cp.async.commit_group;" ::: "memory")
#define CP_WAIT1()  asm volatile("cp.async.wait_group 1;" ::: "memory")
#define CP_WAIT0()  asm volatile("cp.async.wait_group 0;" ::: "memory")

__device__ __forceinline__ uint32_t f2tf32(float f) {
    uint32_t r;
    asm("cvt.rna.tf32.f32 %0, %1;" : "=r"(r) : "f"(f));
    return r;
}

#define MMA_TF32(d, a0, a1, a2, a3, b0, b1) \
    asm volatile( \
        "mma.sync.aligned.m16n8k8.row.col.f32.tf32.tf32.f32 " \
        "{%0,%1,%2,%3}, {%4,%5,%6,%7}, {%8,%9}, {%0,%1,%2,%3};" \
        : "+f"((d)[0]), "+f"((d)[1]), "+f"((d)[2]), "+f"((d)[3]) \
        : "r"(a0), "r"(a1), "r"(a2), "r"(a3), "r"(b0), "r"(b1))

// swizzled smem read (GEMM kernel): row r (stride 32 floats), col c
__device__ __forceinline__ float ldsw(const float* s, int r, int c) {
    return s[r * 32 + ((((c >> 2) ^ (r & 7)) << 2) | (c & 3))];
}

// ---------------------------------------------------------------------------
// Transpose with row padding: out[n][k] = in[k][n]; zero rows n in [inC, outR)
// ---------------------------------------------------------------------------
__global__ void transpose_pad_kernel(const float* __restrict__ in, float* __restrict__ out,
                                     int inR, int inC, int outR)
{
    __shared__ float t[32][33];
    int kb = blockIdx.y * 32, nb = blockIdx.x * 32;
    int x = threadIdx.x, y = threadIdx.y;
    for (int i = y; i < 32; i += 8) {
        int k = kb + i, n = nb + x;
        t[i][x] = (k < inR && n < inC) ? in[(size_t)k * inC + n] : 0.f;
    }
    __syncthreads();
    for (int i = y; i < 32; i += 8) {
        int n = nb + i, k = kb + x;
        if (n < outR && k < inR) out[(size_t)n * inR + k] = t[x][i];
    }
}

// ---------------------------------------------------------------------------
// TF32 mma.sync GEMM with cp.async 3-stage pipeline (unchanged, passing).
// ---------------------------------------------------------------------------
__device__ __forceinline__ void fill_stage(uint32_t sbase,
    const float* __restrict__ A, const float* __restrict__ Bt,
    int m0, int n0, int K, int k0, int tid)
{
    const float* Ab = A + (size_t)m0 * K + k0;
#pragma unroll
    for (int i = 0; i < 4; i++) {
        int idx = tid + i * 256;
        int r = idx >> 3, q = idx & 7;
        uint32_t off = (uint32_t)(r * 128 + ((q ^ (r & 7)) * 16));
        cp16(sbase + off, Ab + (size_t)r * K + q * 4);
    }
    const float* Bb = Bt + (size_t)n0 * K + k0;
#pragma unroll
    for (int i = 0; i < 4; i++) {
        int idx = tid + i * 256;
        int r = idx >> 3, q = idx & 7;
        uint32_t off = (uint32_t)(r * 128 + ((q ^ (r & 7)) * 16));
        cp16(sbase + (uint32_t)STAGE_F * 4 + off, Bb + (size_t)r * K + q * 4);
    }
}

__global__ __launch_bounds__(256) void gemm_mma_kernel(
    const float* __restrict__ A, const float* __restrict__ Bt,
    const float* __restrict__ bias, float* __restrict__ C,
    int M, int Nn, int K)
{
    extern __shared__ float sm[];
    const uint32_t sb = smem_u32(sm);

    const int tid = threadIdx.x;
    const int wid = tid >> 5, lane = tid & 31;
    const int g = lane >> 2, tg = lane & 3;
    const int wm = (wid >> 2) * 64;
    const int wn = (wid & 3) * 32;
    const int m0 = blockIdx.y * MT;
    const int n0 = blockIdx.x * NT;
    const int nk = K / KC;

    float acc[4][4][4];
#pragma unroll
    for (int mi = 0; mi < 4; mi++)
#pragma unroll
        for (int nj = 0; nj < 4; nj++)
#pragma unroll
            for (int q = 0; q < 4; q++) acc[mi][nj][q] = 0.f;

    fill_stage(sb, A, Bt, m0, n0, K, 0, tid);
    CP_COMMIT();
    fill_stage(sb + STAGE_BYTES, A, Bt, m0, n0, K, KC, tid);
    CP_COMMIT();

    for (int kt = 0; kt < nk; kt++) {
        CP_WAIT1();
        __syncthreads();
        if (kt + 2 < nk)
            fill_stage(sb + (uint32_t)((kt + 2) % 3) * STAGE_BYTES,
                       A, Bt, m0, n0, K, (kt + 2) * KC, tid);
        CP_COMMIT();

        const float* a_s = sm + (size_t)(kt % 3) * (2 * STAGE_F);
        const float* b_s = a_s + STAGE_F;
#pragma unroll
        for (int ks = 0; ks < 4; ks++) {
            const int kk = ks * 8;
            uint32_t a[4][4], b[4][2];
#pragma unroll
            for (int mi = 0; mi < 4; mi++) {
                const int row = wm + mi * 16;
                a[mi][0] = __float_as_uint(ldsw(a_s, row + g,     kk + tg));
                a[mi][1] = __float_as_uint(ldsw(a_s, row + g + 8, kk + tg));
                a[mi][2] = __float_as_uint(ldsw(a_s, row + g,     kk + tg + 4));
                a[mi][3] = __float_as_uint(ldsw(a_s, row + g + 8, kk + tg + 4));
            }
#pragma unroll
            for (int nj = 0; nj < 4; nj++) {
                const int col = wn + nj * 8;
                b[nj][0] = __float_as_uint(ldsw(b_s, col + g, kk + tg));
                b[nj][1] = __float_as_uint(ldsw(b_s, col + g, kk + tg + 4));
            }
#pragma unroll
            for (int mi = 0; mi < 4; mi++)
#pragma unroll
                for (int nj = 0; nj < 4; nj++)
                    MMA_TF32(acc[mi][nj], a[mi][0], a[mi][1], a[mi][2], a[mi][3],
                             b[nj][0], b[nj][1]);
        }
        __syncthreads();
    }

#pragma unroll
    for (int nj = 0; nj < 4; nj++) {
        const int gc = n0 + wn + nj * 8 + tg * 2;
        if (gc >= Nn) continue;
        const float bx = bias[gc], by = bias[gc + 1];
#pragma unroll
        for (int mi = 0; mi < 4; mi++) {
            const int row = m0 + wm + mi * 16 + g;
            float2 s0 = make_float2(acc[mi][nj][0] + bx, acc[mi][nj][1] + by);
            float2 s1 = make_float2(acc[mi][nj][2] + bx, acc[mi][nj][3] + by);
            *(float2*)&C[(size_t)row * Nn + gc] = s0;
            *(float2*)&C[(size_t)(row + 8) * Nn + gc] = s1;
        }
    }
}

// ---------------------------------------------------------------------------
// SwiGLU fast-weight update + x1 apply, all GEMM phases on mma.sync tf32.
// One block per (b,h), 8 warps. Smem layout (floats, LD=72):
//   W1t/W2t [64][72]  weights transposed [e][d] (tf32-rounded, updated in place)
//   EA/EG   [128][72] per-tile error matrices [n][e] (tf32-rounded)
//   KS      2x[128][72] double-buffered K/Q tiles (cp.async + in-place rna cvt)
//   CS      [128] column sums for norms
// ---------------------------------------------------------------------------
#define LDS_W 72
#define SW_W1 0
#define SW_W2 4608
#define SW_EA 9216
#define SW_EG 18432
#define SW_KS 27648
#define SW_CS 46080
#define SW_TOT 46208
#define SW_BYTES (SW_TOT * 4)

__device__ __forceinline__ void sw_cp_tile(uint32_t dst, const float* src, int tid) {
#pragma unroll
    for (int i = 0; i < 8; i++) {
        int idx = tid + i * 256;
        int r = idx >> 4, c4 = (idx & 15) << 2;
        cp16(dst + (uint32_t)(r * LDS_W + c4) * 4u, src + (size_t)r * OUTF + c4);
    }
}

__global__ __launch_bounds__(256) void swiglu_mma_kernel(
    const float* __restrict__ w1, const float* __restrict__ w2)
{
    extern __shared__ float sw[];
    float* W1t = sw + SW_W1;
    float* W2t = sw + SW_W2;
    float* EA  = sw + SW_EA;
    float* EG  = sw + SW_EG;
    float* KS  = sw + SW_KS;
    float* CS  = sw + SW_CS;
    const uint32_t ks_addr0 = smem_u32(sw + SW_KS);

    const int b = blockIdx.x / HH, h = blockIdx.x % HH;
    const int tid = threadIdx.x;
    const int wid = tid >> 5, lane = tid & 31;
    const int g = lane >> 2, tg = lane & 3;
    const int wr = wid * 16;            // phase A/C row strip
    const int ds = (wid & 3) * 16;      // phase B d strip

    // init weights transposed + tf32-rounded
    for (int i = tid; i < DD * DD; i += 256) {
        int d = i >> 6, e = i & 63;
        W1t[e * LDS_W + d] = __uint_as_float(f2tf32(w1[h * DD * DD + i]));
        W2t[e * LDS_W + d] = __uint_as_float(f2tf32(w2[h * DD * DD + i]));
    }
    if (tid < 128) CS[tid] = 0.f;

    float G[8][4];
#pragma unroll
    for (int nt = 0; nt < 8; nt++)
#pragma unroll
        for (int q = 0; q < 4; q++) G[nt][q] = 0.f;

    const size_t rowbase = (size_t)b * NSEQ;
    const float* kcol = g_qkv + rowbase * OUTF + CC + h * DD;
    const float* qcol = g_qkv + rowbase * OUTF + h * DD;
    const float* vcol = g_qkv + rowbase * OUTF + 2 * CC + h * DD;

    sw_cp_tile(ks_addr0, kcol, tid);
    CP_COMMIT();

    for (int t = 0; t < 8; t++) {
        CP_WAIT0();
        __syncthreads();
        float* ksb = KS + (t & 1) * 9216;
        // in-place rna tf32 conversion of the arrived tile
#pragma unroll
        for (int i = 0; i < 8; i++) {
            int idx = tid + i * 256;
            int r = idx >> 4, c4 = (idx & 15) << 2;
            float4 v = *(float4*)&ksb[r * LDS_W + c4];
            v.x = __uint_as_float(f2tf32(v.x)); v.y = __uint_as_float(f2tf32(v.y));
            v.z = __uint_as_float(f2tf32(v.z)); v.w = __uint_as_float(f2tf32(v.w));
            *(float4*)&ksb[r * LDS_W + c4] = v;
        }
        __syncthreads();
        if (t < 7)
            sw_cp_tile(ks_addr0 + (uint32_t)(((t + 1) & 1) * 9216 * 4),
                       kcol + (size_t)(t + 1) * 128 * OUTF, tid);
        CP_COMMIT();

        // ---- phase A: Z1/Z2 = K @ W ----
        float z1[8][4], z2[8][4];
#pragma unroll
        for (int nt = 0; nt < 8; nt++)
#pragma unroll
            for (int q = 0; q < 4; q++) { z1[nt][q] = 0.f; z2[nt][q] = 0.f; }
#pragma unroll
        for (int ks = 0; ks < 8; ks++) {
            const int kk = ks * 8;
            uint32_t a0 = __float_as_uint(ksb[(wr + g)     * LDS_W + kk + tg]);
            uint32_t a1 = __float_as_uint(ksb[(wr + g + 8) * LDS_W + kk + tg]);
            uint32_t a2 = __float_as_uint(ksb[(wr + g)     * LDS_W + kk + tg + 4]);
            uint32_t a3 = __float_as_uint(ksb[(wr + g + 8) * LDS_W + kk + tg + 4]);
#pragma unroll
            for (int nt = 0; nt < 8; nt++) {
                uint32_t b0 = __float_as_uint(W1t[(nt * 8 + g) * LDS_W + kk + tg]);
                uint32_t b1 = __float_as_uint(W1t[(nt * 8 + g) * LDS_W + kk + tg + 4]);
                MMA_TF32(z1[nt], a0, a1, a2, a3, b0, b1);
                uint32_t c0 = __float_as_uint(W2t[(nt * 8 + g) * LDS_W + kk + tg]);
                uint32_t c1 = __float_as_uint(W2t[(nt * 8 + g) * LDS_W + kk + tg + 4]);
                MMA_TF32(z2[nt], a0, a1, a2, a3, c0, c1);
            }
        }
        // ---- elementwise: ea, eg (tf32-rounded into EA/EG [n][e]) ----
#pragma unroll
        for (int nt = 0; nt < 8; nt++) {
#pragma unroll
            for (int rp = 0; rp < 2; rp++) {
                const int row = wr + g + rp * 8;
                float2 v2 = *(const float2*)(vcol + (size_t)(t * 128 + row) * OUTF
                                             + nt * 8 + tg * 2);
                float zz2 = z2[nt][rp * 2],     zz1 = z1[nt][rp * 2];
                float ev  = ESC_CONST * v2.x;
                float s   = 1.f / (1.f + __expf(-zz2));
                float ea0 = ev * zz2 * s;
                float eg0 = ev * zz1 * (s * (1.f + zz2 * (1.f - s)));
                zz2 = z2[nt][rp * 2 + 1]; zz1 = z1[nt][rp * 2 + 1];
                ev  = ESC_CONST * v2.y;
                s   = 1.f / (1.f + __expf(-zz2));
                float ea1 = ev * zz2 * s;
                float eg1 = ev * zz1 * (s * (1.f + zz2 * (1.f - s)));
                *(float2*)&EA[row * LDS_W + nt * 8 + tg * 2] =
                    make_float2(__uint_as_float(f2tf32(ea0)), __uint_as_float(f2tf32(ea1)));
                *(float2*)&EG[row * LDS_W + nt * 8 + tg * 2] =
                    make_float2(__uint_as_float(f2tf32(eg0)), __uint_as_float(f2tf32(eg1)));
            }
        }
        __syncthreads();
        // ---- phase B: G += K^T @ (EA or EG), reading Ks/EA transposed ----
        const float* bbp = (wid < 4) ? EA : EG;
#pragma unroll
        for (int ks = 0; ks < 16; ks++) {
            const int kk = ks * 8;
            uint32_t a0 = __float_as_uint(ksb[(kk + tg)     * LDS_W + ds + g]);
            uint32_t a1 = __float_as_uint(ksb[(kk + tg)     * LDS_W + ds + g + 8]);
            uint32_t a2 = __float_as_uint(ksb[(kk + tg + 4) * LDS_W + ds + g]);
            uint32_t a3 = __float_as_uint(ksb[(kk + tg + 4) * LDS_W + ds + g + 8]);
#pragma unroll
            for (int nt = 0; nt < 8; nt++) {
                uint32_t b0 = __float_as_uint(bbp[(kk + tg)     * LDS_W + nt * 8 + g]);
                uint32_t b1 = __float_as_uint(bbp[(kk + tg + 4) * LDS_W + nt * 8 + g]);
                MMA_TF32(G[nt], a0, a1, a2, a3, b0, b1);
            }
        }
        // next iteration's top __syncthreads orders phase B reads vs EA rewrites
    }

    // ---- column norms (over d) + weight update ----
#pragma unroll
    for (int nt = 0; nt < 8; nt++)
#pragma unroll
        for (int par = 0; par < 2; par++) {
            float s = G[nt][par] * G[nt][par] + G[nt][2 + par] * G[nt][2 + par];
            s += __shfl_xor_sync(0xffffffffu, s, 4);
            s += __shfl_xor_sync(0xffffffffu, s, 8);
            s += __shfl_xor_sync(0xffffffffu, s, 16);
            if (g == 0)
                atomicAdd(&CS[((wid < 4) ? 0 : 64) + nt * 8 + tg * 2 + par], s);
        }
    __syncthreads();
    {
        float* wt = (wid < 4) ? W1t : W2t;
        const int cb = (wid < 4) ? 0 : 64;
#pragma unroll
        for (int nt = 0; nt < 8; nt++)
#pragma unroll
            for (int par = 0; par < 2; par++) {
                const int col = nt * 8 + tg * 2 + par;
                float iv = 1.f / (sqrtf(CS[cb + col]) + 1.f);
                float n0 = wt[col * LDS_W + ds + g]     - G[nt][par]     * iv;
                float n1 = wt[col * LDS_W + ds + g + 8] - G[nt][2 + par] * iv;
                wt[col * LDS_W + ds + g]     = __uint_as_float(f2tf32(n0));
                wt[col * LDS_W + ds + g + 8] = __uint_as_float(f2tf32(n1));
            }
    }
    __syncthreads();

    // ---- phase C: x1 = (Q @ W1u) * silu(Q @ W2u) ----
    sw_cp_tile(ks_addr0, qcol, tid);
    CP_COMMIT();
    for (int t = 0; t < 8; t++) {
        CP_WAIT0();
        __syncthreads();
        float* ksb = KS + (t & 1) * 9216;
#pragma unroll
        for (int i = 0; i < 8; i++) {
            int idx = tid + i * 256;
            int r = idx >> 4, c4 = (idx & 15) << 2;
            float4 v = *(float4*)&ksb[r * LDS_W + c4];
            v.x = __uint_as_float(f2tf32(v.x)); v.y = __uint_as_float(f2tf32(v.y));
            v.z = __uint_as_float(f2tf32(v.z)); v.w = __uint_as_float(f2tf32(v.w));
            *(float4*)&ksb[r * LDS_W + c4] = v;
        }
        __syncthreads();
        if (t < 7)
            sw_cp_tile(ks_addr0 + (uint32_t)(((t + 1) & 1) * 9216 * 4),
                       qcol + (size_t)(t + 1) * 128 * OUTF, tid);
        CP_COMMIT();

        float y1[8][4], y2[8][4];
#pragma unroll
        for (int nt = 0; nt < 8; nt++)
#pragma unroll
            for (int q = 0; q < 4; q++) { y1[nt][q] = 0.f; y2[nt][q] = 0.f; }
#pragma unroll
        for (int ks = 0; ks < 8; ks++) {
            const int kk = ks * 8;
            uint32_t a0 = __float_as_uint(ksb[(wr + g)     * LDS_W + kk + tg]);
            uint32_t a1 = __float_as_uint(ksb[(wr + g + 8) * LDS_W + kk + tg]);
            uint32_t a2 = __float_as_uint(ksb[(wr + g)     * LDS_W + kk + tg + 4]);
            uint32_t a3 = __float_as_uint(ksb[(wr + g + 8) * LDS_W + kk + tg + 4]);
#pragma unroll
            for (int nt = 0; nt < 8; nt++) {
                uint32_t b0 = __float_as_uint(W1t[(nt * 8 + g) * LDS_W + kk + tg]);
                uint32_t b1 = __float_as_uint(W1t[(nt * 8 + g) * LDS_W + kk + tg + 4]);
                MMA_TF32(y1[nt], a0, a1, a2, a3, b0, b1);
                uint32_t c0 = __float_as_uint(W2t[(nt * 8 + g) * LDS_W + kk + tg]);
                uint32_t c1 = __float_as_uint(W2t[(nt * 8 + g) * LDS_W + kk + tg + 4]);
                MMA_TF32(y2[nt], a0, a1, a2, a3, c0, c1);
            }
        }
#pragma unroll
        for (int nt = 0; nt < 8; nt++)
#pragma unroll
            for (int rp = 0; rp < 2; rp++) {
                const int row = t * 128 + wr + g + rp * 8;
                float yv = y2[nt][rp * 2];
                float s  = 1.f / (1.f + __expf(-yv));
                float o0 = y1[nt][rp * 2] * yv * s;
                yv = y2[nt][rp * 2 + 1];
                s  = 1.f / (1.f + __expf(-yv));
                float o1 = y1[nt][rp * 2 + 1] * yv * s;
                *(float2*)&g_xcat[(rowbase + row) * XCATC + h * DD + nt * 8 + tg * 2] =
                    make_float2(o0, o1);
            }
    }
}

// ---------------------------------------------------------------------------
// Fused per-(b,d) depthwise-conv fast-weight update + conv apply.
// ---------------------------------------------------------------------------
__global__ __launch_bounds__(256) void dwc_x2_kernel(const float* __restrict__ w3)
{
    __shared__ float q2s[1024], k2s[1024], es[1024];
    __shared__ float gsum[9];
    __shared__ float w3s[9];

    const int b = blockIdx.x >> 6;
    const int d = blockIdx.x & 63;
    const int tid = threadIdx.x;

    for (int i = tid; i < 1024; i += 256) {
        size_t base = (size_t)(b * NSEQ + i) * OUTF + 3 * CC + d;
        q2s[i] = g_qkv[base];
        k2s[i] = g_qkv[base + DD];
        es[i]  = g_qkv[base + 2 * DD] * ESC_CONST;
    }
    if (tid < 9) gsum[tid] = 0.f;
    __syncthreads();

    float p[9];
#pragma unroll
    for (int j = 0; j < 9; j++) p[j] = 0.f;
    for (int i = tid; i < 1024; i += 256) {
        int y = i >> 5, x = i & 31;
        float e = es[i];
#pragma unroll
        for (int ky = 0; ky < 3; ky++) {
            int yy = y + ky - 1;
            if (yy < 0 || yy > 31) continue;
#pragma unroll
            for (int kx = 0; kx < 3; kx++) {
                int xx = x + kx - 1;
                if (xx >= 0 && xx <= 31) p[ky * 3 + kx] += k2s[yy * 32 + xx] * e;
            }
        }
    }
#pragma unroll
    for (int j = 0; j < 9; j++) {
        float v = p[j];
#pragma unroll
        for (int o = 16; o > 0; o >>= 1) v += __shfl_down_sync(0xffffffffu, v, o);
        if ((tid & 31) == 0) atomicAdd(&gsum[j], v);
    }
    __syncthreads();
    if (tid == 0) {
        float nrm = 0.f;
#pragma unroll
        for (int j = 0; j < 9; j++) nrm += gsum[j] * gsum[j];
        float inv = 1.f / (sqrtf(nrm) + 1.f);
#pragma unroll
        for (int j = 0; j < 9; j++) w3s[j] = w3[d * 9 + j] - gsum[j] * inv;
    }
    __syncthreads();

    for (int i = tid; i < 1024; i += 256) {
        int y = i >> 5, x = i & 31;
        float acc = 0.f;
#pragma unroll
        for (int ky = 0; ky < 3; ky++) {
            int yy = y + ky - 1;
            if (yy < 0 || yy > 31) continue;
#pragma unroll
            for (int kx = 0; kx < 3; kx++) {
                int xx = x + kx - 1;
                if (xx >= 0 && xx <= 31) acc += q2s[yy * 32 + xx] * w3s[ky * 3 + kx];
            }
        }
        g_xcat[(size_t)(b * NSEQ + i) * XCATC + CC + d] = acc;
    }
}

// ---------------------------------------------------------------------------
// Launch
// ---------------------------------------------------------------------------
extern "C" void kernel_launch(void* const* d_in, const int* in_sizes, int n_in,
                              void* d_out, int out_size)
{
    const float* x      = (const float*)d_in[0];
    const float* W_qkv  = (const float*)d_in[1];
    const float* b_qkv  = (const float*)d_in[2];
    const float* w1     = (const float*)d_in[3];
    const float* w2     = (const float*)d_in[4];
    const float* w3     = (const float*)d_in[5];
    const float* proj_W = (const float*)d_in[6];
    const float* proj_b = (const float*)d_in[7];
    float* out = (float*)d_out;

    float *qkv, *xcat, *Wt1, *Wt2;
    cudaGetSymbolAddress((void**)&qkv,  g_qkv);
    cudaGetSymbolAddress((void**)&xcat, g_xcat);
    cudaGetSymbolAddress((void**)&Wt1,  g_Wt1);
    cudaGetSymbolAddress((void**)&Wt2,  g_Wt2);

    const int SMEM_BYTES = 3 * STAGE_BYTES;  // 98304
    cudaFuncSetAttribute(gemm_mma_kernel, cudaFuncAttributeMaxDynamicSharedMemorySize, SMEM_BYTES);
    cudaFuncSetAttribute(swiglu_mma_kernel, cudaFuncAttributeMaxDynamicSharedMemorySize, SW_BYTES);

    // Transposes: Wt1[n][k] = W_qkv[k][n] (pad to 2560 rows); Wt2[n][k] = proj_W[k][n]
    {
        dim3 blk(32, 8);
        transpose_pad_kernel<<<dim3(2560 / 32, CC / 32), blk>>>(W_qkv, Wt1, CC, OUTF, 2560);
        transpose_pad_kernel<<<dim3(CC / 32, XCATC / 32), blk>>>(proj_W, Wt2, XCATC, CC, CC);
    }
    // GEMM1: qkv = x @ W_qkv + b_qkv   [32768,768] x [768,2496]
    {
        dim3 grid(2560 / NT, MROWS / MT);
        gemm_mma_kernel<<<grid, 256, SMEM_BYTES>>>(x, Wt1, b_qkv, qkv, MROWS, OUTF, CC);
    }
    // SwiGLU fast-weight update + x1 (tensor-core path)
    swiglu_mma_kernel<<<BB * HH, 256, SW_BYTES>>>(w1, w2);
    // DWC fast-weight update + x2
    dwc_x2_kernel<<<BB * DD, 256>>>(w3);
    // GEMM2: out = xcat @ proj_W + proj_b   [32768,832] x [832,768]
    {
        dim3 grid(CC / NT, MROWS / MT);
        gemm_mma_kernel<<<grid, 256, SMEM_BYTES>>>(xcat, Wt2, proj_b, out, MROWS, CC, XCATC);
    }
}